// round 1
// baseline (speedup 1.0000x reference)
#include <cuda_runtime.h>

// ---------------------------------------------------------------------------
// VQ-EMA forward: distances GEMM + argmin + one-hot + gather + scalars.
// T = 32768 rows (b*1024 + j*32 + d), D = 64, K = 1024.
// Output layout (fp32, concatenated in reference return order):
//   [0)          quantized_out [32,64,32,32]   (2,097,152)
//   [2097152)    loss (1)
//   [2097153)    perplexity (1)
//   [2097154)    encodings [32768,1024]        (33,554,432)
//   [35651586)   distances [32768,1024]        (33,554,432)
// ---------------------------------------------------------------------------

#define ED 64
#define T_ROWS 32768
#define K_CODES 1024

#define OFF_Q    0ull
#define OFF_LOSS 2097152ull
#define OFF_PERP 2097153ull
#define OFF_ENC  2097154ull
#define OFF_DIST 35651586ull

__device__ int   g_idx[T_ROWS];
__device__ int   g_counts[K_CODES];
__device__ float g_loss_sum;
__device__ float g_wnorm[K_CODES];

// --- kernel 0: codebook norms + zero scratch (replay-safe) -----------------
__global__ void k_init(const float* __restrict__ W) {
    int k = blockIdx.x * blockDim.x + threadIdx.x;
    if (k < K_CODES) {
        const float* w = W + (size_t)k * ED;
        float s = 0.f;
        #pragma unroll
        for (int d = 0; d < ED; d++) s += w[d] * w[d];
        g_wnorm[k] = s;
        g_counts[k] = 0;
    }
    if (k == 0) g_loss_sum = 0.f;
}

// --- kernel 1: distances GEMM + fused argmin + loss accumulation -----------
// grid = 1024 blocks, each handles 32 rows x all 1024 codes (8 chunks of 128).
__global__ __launch_bounds__(256, 1)
void k_dist(const float* __restrict__ latent,
            const float* __restrict__ W,
            float* __restrict__ out) {
    __shared__ float xT[ED][32];      // transposed x tile  (d-major)
    __shared__ float wT[ED][128];     // transposed W chunk (d-major)
    __shared__ float wn_s[128];
    __shared__ float xnorm[32];
    __shared__ float rowmin[32];
    __shared__ int   rowidx[32];

    const int tid = threadIdx.x;
    const int blk = blockIdx.x;
    const int b = blk >> 5;                 // 32 blocks per batch index
    const int rem_base = (blk & 31) * 32;   // j*32+d offset within batch

    // load x tile: flat[t][n] = latent[(b*64+n)*1024 + rem]
    {
        const int tl = tid & 31;
        const int n0 = (tid >> 5) * 8;
        const float* lp = latent + ((size_t)b * ED) * 1024 + rem_base + tl;
        #pragma unroll
        for (int i = 0; i < 8; i++)
            xT[n0 + i][tl] = lp[(size_t)(n0 + i) * 1024];
    }
    __syncthreads();

    if (tid < 32) {
        float s = 0.f;
        #pragma unroll
        for (int d = 0; d < ED; d++) { float v = xT[d][tid]; s += v * v; }
        xnorm[tid] = s;
        rowmin[tid] = 3.4e38f;
        rowidx[tid] = 0;
    }
    __syncthreads();

    const int r0 = (tid >> 5) * 4;   // each warp owns 4 rows exclusively
    const int c0 = (tid & 31) * 4;   // 4 consecutive codes per lane

    for (int ch = 0; ch < 8; ch++) {
        const int kc0 = ch * 128;

        // load W chunk transposed: conflict-free STS (lanes -> consecutive k)
        {
            const int kl = tid & 127;
            const int dh = (tid >> 7) * 32;
            const float4* wp = (const float4*)(W + (size_t)(kc0 + kl) * ED + dh);
            #pragma unroll
            for (int q = 0; q < 8; q++) {
                float4 v = wp[q];
                int d = dh + q * 4;
                wT[d + 0][kl] = v.x; wT[d + 1][kl] = v.y;
                wT[d + 2][kl] = v.z; wT[d + 3][kl] = v.w;
            }
            if (tid < 128) wn_s[tid] = g_wnorm[kc0 + tid];
        }
        __syncthreads();

        float acc[4][4] = {};
        #pragma unroll 16
        for (int d = 0; d < ED; d++) {
            float4 a = *(const float4*)&xT[d][r0];  // warp-broadcast
            float4 w = *(const float4*)&wT[d][c0];  // conflict-free
            acc[0][0] += a.x * w.x; acc[0][1] += a.x * w.y;
            acc[0][2] += a.x * w.z; acc[0][3] += a.x * w.w;
            acc[1][0] += a.y * w.x; acc[1][1] += a.y * w.y;
            acc[1][2] += a.y * w.z; acc[1][3] += a.y * w.w;
            acc[2][0] += a.z * w.x; acc[2][1] += a.z * w.y;
            acc[2][2] += a.z * w.z; acc[2][3] += a.z * w.w;
            acc[3][0] += a.w * w.x; acc[3][1] += a.w * w.y;
            acc[3][2] += a.w * w.z; acc[3][3] += a.w * w.w;
        }

        // epilogue: distances out + running argmin per row
        #pragma unroll
        for (int i = 0; i < 4; i++) {
            const int row = blk * 32 + r0 + i;
            const float xni = xnorm[r0 + i];
            float d0 = fmaf(-2.f, acc[i][0], xni + wn_s[c0 + 0]);
            float d1 = fmaf(-2.f, acc[i][1], xni + wn_s[c0 + 1]);
            float d2 = fmaf(-2.f, acc[i][2], xni + wn_s[c0 + 2]);
            float d3 = fmaf(-2.f, acc[i][3], xni + wn_s[c0 + 3]);

            // OFF_DIST is only 8B-aligned -> float2 stores
            float2* dst = (float2*)(out + OFF_DIST + (size_t)row * 1024 + kc0 + c0);
            dst[0] = make_float2(d0, d1);
            dst[1] = make_float2(d2, d3);

            float v = d0; int ii = kc0 + c0;
            if (d1 < v) { v = d1; ii = kc0 + c0 + 1; }
            if (d2 < v) { v = d2; ii = kc0 + c0 + 2; }
            if (d3 < v) { v = d3; ii = kc0 + c0 + 3; }
            #pragma unroll
            for (int off = 16; off > 0; off >>= 1) {
                float ov = __shfl_down_sync(0xffffffffu, v, off);
                int   oi = __shfl_down_sync(0xffffffffu, ii, off);
                if (ov < v || (ov == v && oi < ii)) { v = ov; ii = oi; }
            }
            if ((tid & 31) == 0) {   // warp-exclusive rows -> no race
                if (v < rowmin[r0 + i] ||
                    (v == rowmin[r0 + i] && ii < rowidx[r0 + i])) {
                    rowmin[r0 + i] = v;
                    rowidx[r0 + i] = ii;
                }
            }
        }
        __syncthreads();
    }

    if (tid < 32) {
        const int t = blk * 32 + tid;
        const int idx = rowidx[tid];
        g_idx[t] = idx;
        atomicAdd(&g_counts[idx], 1);
        float lv = rowmin[tid];   // min distance == ||W[idx]-x||^2
        #pragma unroll
        for (int off = 16; off > 0; off >>= 1)
            lv += __shfl_down_sync(0xffffffffu, lv, off);
        if (tid == 0) atomicAdd(&g_loss_sum, lv);
    }
}

// --- kernel 2: one-hot encodings (float2; OFF_ENC only 8B-aligned) ---------
__global__ void k_enc(float* __restrict__ out) {
    const unsigned g = blockIdx.x * 256u + threadIdx.x;  // float2 index
    const int t = g >> 9;              // 512 float2 per row
    const int c = (int)((g & 511u) << 1);
    const int idx = g_idx[t];
    float2 v;
    v.x = (idx == c)     ? 1.f : 0.f;
    v.y = (idx == c + 1) ? 1.f : 0.f;
    ((float2*)(out + OFF_ENC))[g] = v;
}

// --- kernel 3: quantized_out = W[idx] in [b,n,j,d] layout -------------------
__global__ void k_quant(const float* __restrict__ W, float* __restrict__ out) {
    const int e = blockIdx.x * 256 + threadIdx.x;
    const int d_ = e & 31;
    const int j  = (e >> 5) & 31;
    const int n  = (e >> 10) & 63;
    const int b  = e >> 16;
    const int t  = (b << 10) + (j << 5) + d_;
    out[OFF_Q + e] = W[(size_t)g_idx[t] * ED + n];
}

// --- kernel 4: scalars -------------------------------------------------------
__global__ void k_final(float* __restrict__ out) {
    __shared__ float red[1024];
    const int k = threadIdx.x;
    const float p = (float)g_counts[k] / 32768.0f;
    red[k] = -p * logf(p + 1e-10f);
    __syncthreads();
    for (int s = 512; s > 0; s >>= 1) {
        if (k < s) red[k] += red[k + s];
        __syncthreads();
    }
    if (k == 0) {
        out[OFF_PERP] = expf(red[0]);
        out[OFF_LOSS] = 0.25f * g_loss_sum / 2097152.0f;
    }
}

// ---------------------------------------------------------------------------
extern "C" void kernel_launch(void* const* d_in, const int* in_sizes, int n_in,
                              void* d_out, int out_size) {
    const float* latent = (const float*)d_in[0];
    const float* W      = (const float*)d_in[1];
    float* out = (float*)d_out;

    k_init <<<4, 256>>>(W);
    k_dist <<<1024, 256>>>(latent, W, out);
    k_enc  <<<65536, 256>>>(out);
    k_quant<<<8192, 256>>>(W, out);
    k_final<<<1, 1024>>>(out);
}

// round 2
// speedup vs baseline: 1.0262x; 1.0262x over previous
#include <cuda_runtime.h>

// ---------------------------------------------------------------------------
// VQ-EMA forward, fused. T = 32768 rows, D = 64, K = 1024.
// Output layout (fp32):
//   [0)          quantized_out [32,64,32,32]   (2,097,152)
//   [2097152)    loss, [2097153) perplexity
//   [2097154)    encodings [32768,1024]
//   [35651586)   distances [32768,1024]
// ---------------------------------------------------------------------------

#define ED 64
#define T_ROWS 32768
#define K_CODES 1024

#define OFF_Q    0ull
#define OFF_LOSS 2097152ull
#define OFF_PERP 2097153ull
#define OFF_ENC  2097154ull
#define OFF_DIST 35651586ull

typedef unsigned long long ULL;

__device__ int   g_counts[K_CODES];
__device__ float g_loss_sum;
__device__ float g_wnorm[K_CODES];

__device__ __forceinline__ ULL fma2(ULL a, ULL b, ULL c) {
    ULL d;
    asm("fma.rn.f32x2 %0, %1, %2, %3;" : "=l"(d) : "l"(a), "l"(b), "l"(c));
    return d;
}
__device__ __forceinline__ ULL dup2(float v) {
    ULL r;
    asm("mov.b64 %0, {%1, %1};" : "=l"(r) : "f"(v));
    return r;
}
__device__ __forceinline__ float2 unpk(ULL a) {
    float2 f;
    asm("mov.b64 {%0, %1}, %2;" : "=f"(f.x), "=f"(f.y) : "l"(a));
    return f;
}

// --- kernel 0: codebook norms + zero scratch (replay-safe) -----------------
__global__ void k_init(const float* __restrict__ W) {
    int k = blockIdx.x * blockDim.x + threadIdx.x;
    if (k < K_CODES) {
        const float4* w = (const float4*)(W + (size_t)k * ED);
        float s = 0.f;
        #pragma unroll
        for (int q = 0; q < 16; q++) {
            float4 v = w[q];
            s += v.x * v.x + v.y * v.y + v.z * v.z + v.w * v.w;
        }
        g_wnorm[k] = s;
        g_counts[k] = 0;
    }
    if (k == 0) g_loss_sum = 0.f;
}

// --- kernel 1: fused distances + argmin + encodings + quantized + loss -----
// 1024 blocks; block = 32 rows (b = blk>>5, j = blk&31, d = 0..31) x 1024 codes.
// Warp wid: rows (wid&3)*8 .. +7, col-half (wid>>2)*64 within each 128 chunk.
__global__ __launch_bounds__(256)
void k_dist(const float* __restrict__ latent,
            const float* __restrict__ W,
            float* __restrict__ out) {
    __shared__ ULL   xD[ED][32];       // row scalars duplicated as f32x2 (16KB)
    __shared__ float wT[ED][128];      // W chunk transposed, d-major (32KB)
    __shared__ float wn_s[128];
    __shared__ float xnorm[32];
    __shared__ float hmin[2][32];
    __shared__ int   hidx[2][32];
    __shared__ int   rowidx_s[32];
    __shared__ float wq[32][65];       // quant transpose staging (pad: no conflicts)

    const int tid  = threadIdx.x;
    const int blk  = blockIdx.x;
    const int lane = tid & 31;
    const int wid  = tid >> 5;
    const int rg    = wid & 3;         // row group
    const int ch2   = wid >> 2;        // col half
    const int rbase = rg * 8;
    const int cc    = ch2 * 64 + lane * 2;

    const int b        = blk >> 5;
    const int rem_base = (blk & 31) * 32;

    // load x tile duplicated: xD[n][row] = (v, v)
    {
        const int tl = tid & 31;
        const int n0 = (tid >> 5) * 8;
        const float* lp = latent + ((size_t)b * ED) * 1024 + rem_base + tl;
        #pragma unroll
        for (int i = 0; i < 8; i++)
            xD[n0 + i][tl] = dup2(lp[(size_t)(n0 + i) * 1024]);
    }
    __syncthreads();

    if (tid < 32) {
        float s = 0.f;
        #pragma unroll
        for (int d = 0; d < ED; d++) {
            float v = ((const float*)&xD[d][tid])[0];
            s = fmaf(v, v, s);
        }
        xnorm[tid] = s;
    }

    float vmin[8];
    int   imin[8];
    #pragma unroll
    for (int r = 0; r < 8; r++) { vmin[r] = 3.4e38f; imin[r] = 0; }

    for (int ch = 0; ch < 8; ch++) {
        const int kc0 = ch << 7;

        // load W chunk transposed (conflict-free STS) + chunk wnorms
        {
            const int kl = tid & 127;
            const int dh = (tid >> 7) * 32;
            const float4* wp = (const float4*)(W + (size_t)(kc0 + kl) * ED + dh);
            #pragma unroll
            for (int q = 0; q < 8; q++) {
                float4 v = wp[q];
                int d = dh + q * 4;
                wT[d + 0][kl] = v.x; wT[d + 1][kl] = v.y;
                wT[d + 2][kl] = v.z; wT[d + 3][kl] = v.w;
            }
            if (tid < 128) wn_s[tid] = g_wnorm[kc0 + tid];
        }
        __syncthreads();

        ULL acc[8];
        #pragma unroll
        for (int r = 0; r < 8; r++) acc[r] = 0ull;

        #pragma unroll 8
        for (int d = 0; d < ED; d++) {
            ULL w2 = *(const ULL*)&wT[d][cc];                      // 8B, conflict-free
            ulonglong2 a01 = *(const ulonglong2*)&xD[d][rbase];    // broadcasts
            ulonglong2 a23 = *(const ulonglong2*)&xD[d][rbase + 2];
            ulonglong2 a45 = *(const ulonglong2*)&xD[d][rbase + 4];
            ulonglong2 a67 = *(const ulonglong2*)&xD[d][rbase + 6];
            acc[0] = fma2(a01.x, w2, acc[0]);
            acc[1] = fma2(a01.y, w2, acc[1]);
            acc[2] = fma2(a23.x, w2, acc[2]);
            acc[3] = fma2(a23.y, w2, acc[3]);
            acc[4] = fma2(a45.x, w2, acc[4]);
            acc[5] = fma2(a45.y, w2, acc[5]);
            acc[6] = fma2(a67.x, w2, acc[6]);
            acc[7] = fma2(a67.y, w2, acc[7]);
        }

        // epilogue: distances + encoding zeros + per-lane running argmin
        const int cg0 = kc0 + cc;
        const float wn0 = wn_s[cc];
        const float wn1 = wn_s[cc + 1];
        #pragma unroll
        for (int r = 0; r < 8; r++) {
            const int row = rbase + r;
            const float xn = xnorm[row];
            float2 dot = unpk(acc[r]);
            float d0 = fmaf(-2.f, dot.x, xn + wn0);
            float d1 = fmaf(-2.f, dot.y, xn + wn1);
            size_t rb = (size_t)(blk * 32 + row) * 1024 + cg0;
            *(float2*)(out + OFF_DIST + rb) = make_float2(d0, d1);
            *(float2*)(out + OFF_ENC + rb) = make_float2(0.f, 0.f);
            if (d0 < vmin[r]) { vmin[r] = d0; imin[r] = cg0; }
            if (d1 < vmin[r]) { vmin[r] = d1; imin[r] = cg0 + 1; }
        }
        __syncthreads();
    }

    // warp-level argmin reduce (col-half partial), then combine halves
    #pragma unroll
    for (int r = 0; r < 8; r++) {
        float v = vmin[r];
        int   ii = imin[r];
        #pragma unroll
        for (int off = 16; off > 0; off >>= 1) {
            float ov = __shfl_down_sync(0xffffffffu, v, off);
            int   oi = __shfl_down_sync(0xffffffffu, ii, off);
            if (ov < v || (ov == v && oi < ii)) { v = ov; ii = oi; }
        }
        if (lane == 0) { hmin[ch2][rbase + r] = v; hidx[ch2][rbase + r] = ii; }
    }
    __syncthreads();

    if (tid < 32) {
        float v0 = hmin[0][tid], v1 = hmin[1][tid];
        int   i0 = hidx[0][tid], i1 = hidx[1][tid];
        bool sel = (v1 < v0) || (v1 == v0 && i1 < i0);
        float v = sel ? v1 : v0;
        int  ii = sel ? i1 : i0;
        rowidx_s[tid] = ii;
        atomicAdd(&g_counts[ii], 1);
        // the '1' in one-hot: ordered after this block's zero-stores by syncthreads
        out[OFF_ENC + (size_t)(blk * 32 + tid) * 1024 + ii] = 1.f;
        // loss: min distance == ||W[idx] - x||^2
        float lv = v;
        #pragma unroll
        for (int off = 16; off > 0; off >>= 1)
            lv += __shfl_down_sync(0xffffffffu, lv, off);
        if (tid == 0) atomicAdd(&g_loss_sum, lv);
    }
    __syncthreads();

    // fused quantized gather: stage W[idx] rows coalesced, write transposed
    #pragma unroll
    for (int i = 0; i < 2; i++) {
        int fid = tid + i * 256;
        int r   = fid >> 4;     // 0..31 (local d index)
        int c4  = fid & 15;
        float4 v = ((const float4*)(W + (size_t)rowidx_s[r] * ED))[c4];
        wq[r][c4 * 4 + 0] = v.x; wq[r][c4 * 4 + 1] = v.y;
        wq[r][c4 * 4 + 2] = v.z; wq[r][c4 * 4 + 3] = v.w;
    }
    __syncthreads();
    {
        const int jb = (blk & 31) * 32;
        #pragma unroll
        for (int i = 0; i < 8; i++) {
            int eid = tid + i * 256;       // 0..2047
            int n   = eid >> 5;
            int dd  = eid & 31;
            out[OFF_Q + ((size_t)(b * ED + n)) * 1024 + jb + dd] = wq[dd][n];
        }
    }
}

// --- kernel 2: scalars -------------------------------------------------------
__global__ void k_final(float* __restrict__ out) {
    __shared__ float red[1024];
    const int k = threadIdx.x;
    const float p = (float)g_counts[k] / 32768.0f;
    red[k] = -p * logf(p + 1e-10f);
    __syncthreads();
    for (int s = 512; s > 0; s >>= 1) {
        if (k < s) red[k] += red[k + s];
        __syncthreads();
    }
    if (k == 0) {
        out[OFF_PERP] = expf(red[0]);
        out[OFF_LOSS] = 0.25f * g_loss_sum / 2097152.0f;
    }
}

// ---------------------------------------------------------------------------
extern "C" void kernel_launch(void* const* d_in, const int* in_sizes, int n_in,
                              void* d_out, int out_size) {
    const float* latent = (const float*)d_in[0];
    const float* W      = (const float*)d_in[1];
    float* out = (float*)d_out;

    k_init <<<4, 256>>>(W);
    k_dist <<<1024, 256>>>(latent, W, out);
    k_final<<<1, 1024>>>(out);
}

// round 3
// speedup vs baseline: 1.0275x; 1.0013x over previous
#include <cuda_runtime.h>

// ---------------------------------------------------------------------------
// VQ-EMA forward, fused. T = 32768 rows, D = 64, K = 1024.
// Output layout (fp32):
//   [0)          quantized_out [32,64,32,32]   (2,097,152)
//   [2097152)    loss, [2097153) perplexity
//   [2097154)    encodings [32768,1024]
//   [35651586)   distances [32768,1024]
// ---------------------------------------------------------------------------

#define ED 64
#define T_ROWS 32768
#define K_CODES 1024

#define OFF_Q    0ull
#define OFF_LOSS 2097152ull
#define OFF_PERP 2097153ull
#define OFF_ENC  2097154ull
#define OFF_DIST 35651586ull

typedef unsigned long long ULL;

__device__ int   g_counts[K_CODES];
__device__ float g_loss_sum;
__device__ float g_wnorm[K_CODES];

__device__ __forceinline__ ULL fma2(ULL a, ULL b, ULL c) {
    ULL d;
    asm("fma.rn.f32x2 %0, %1, %2, %3;" : "=l"(d) : "l"(a), "l"(b), "l"(c));
    return d;
}
__device__ __forceinline__ ULL dup2(float v) {
    ULL r;
    asm("mov.b64 %0, {%1, %1};" : "=l"(r) : "f"(v));
    return r;
}
__device__ __forceinline__ float2 unpk(ULL a) {
    float2 f;
    asm("mov.b64 {%0, %1}, %2;" : "=f"(f.x), "=f"(f.y) : "l"(a));
    return f;
}

// --- kernel 0: codebook norms + zero scratch (replay-safe) -----------------
__global__ void k_init(const float* __restrict__ W) {
    int k = blockIdx.x * blockDim.x + threadIdx.x;
    if (k < K_CODES) {
        const float4* w = (const float4*)(W + (size_t)k * ED);
        float s = 0.f;
        #pragma unroll
        for (int q = 0; q < 16; q++) {
            float4 v = w[q];
            s += v.x * v.x + v.y * v.y + v.z * v.z + v.w * v.w;
        }
        g_wnorm[k] = s;
        g_counts[k] = 0;
    }
    if (k == 0) g_loss_sum = 0.f;
}

// --- kernel 1: fused distances + argmin + encodings + quantized + loss -----
// 1024 blocks; block = 32 rows (b = blk>>5, j = blk&31, d = 0..31) x 1024 codes.
// Warp wid: rows (wid&3)*8 .. +7, col-half (wid>>2)*64 within each 128 chunk.
__global__ __launch_bounds__(256)
void k_dist(const float* __restrict__ latent,
            const float* __restrict__ W,
            float* __restrict__ out) {
    __shared__ ULL   xD[ED][32];       // row scalars duplicated as f32x2 (16KB)
    __shared__ float wT[ED][128];      // W chunk transposed, d-major (32KB)
    __shared__ float wn_s[128];
    __shared__ float xnorm[32];
    __shared__ float hmin[2][32];
    __shared__ int   hidx[2][32];
    __shared__ int   rowidx_s[32];
    __shared__ float wq[32][65];       // quant transpose staging (pad: no conflicts)

    const int tid  = threadIdx.x;
    const int blk  = blockIdx.x;
    const int lane = tid & 31;
    const int wid  = tid >> 5;
    const int rg    = wid & 3;         // row group
    const int ch2   = wid >> 2;        // col half
    const int rbase = rg * 8;
    const int cc    = ch2 * 64 + lane * 2;

    const int b        = blk >> 5;
    const int rem_base = (blk & 31) * 32;

    // load x tile duplicated: xD[n][row] = (v, v)
    {
        const int tl = tid & 31;
        const int n0 = (tid >> 5) * 8;
        const float* lp = latent + ((size_t)b * ED) * 1024 + rem_base + tl;
        #pragma unroll
        for (int i = 0; i < 8; i++)
            xD[n0 + i][tl] = dup2(lp[(size_t)(n0 + i) * 1024]);
    }
    __syncthreads();

    if (tid < 32) {
        float s = 0.f;
        #pragma unroll
        for (int d = 0; d < ED; d++) {
            float v = ((const float*)&xD[d][tid])[0];
            s = fmaf(v, v, s);
        }
        xnorm[tid] = s;
    }

    float vmin[8];
    int   imin[8];
    #pragma unroll
    for (int r = 0; r < 8; r++) { vmin[r] = 3.4e38f; imin[r] = 0; }

    for (int ch = 0; ch < 8; ch++) {
        const int kc0 = ch << 7;

        // load W chunk transposed (conflict-free STS) + chunk wnorms
        {
            const int kl = tid & 127;
            const int dh = (tid >> 7) * 32;
            const float4* wp = (const float4*)(W + (size_t)(kc0 + kl) * ED + dh);
            #pragma unroll
            for (int q = 0; q < 8; q++) {
                float4 v = wp[q];
                int d = dh + q * 4;
                wT[d + 0][kl] = v.x; wT[d + 1][kl] = v.y;
                wT[d + 2][kl] = v.z; wT[d + 3][kl] = v.w;
            }
            if (tid < 128) wn_s[tid] = g_wnorm[kc0 + tid];
        }
        __syncthreads();

        ULL acc[8];
        #pragma unroll
        for (int r = 0; r < 8; r++) acc[r] = 0ull;

        #pragma unroll 8
        for (int d = 0; d < ED; d++) {
            ULL w2 = *(const ULL*)&wT[d][cc];                      // 8B, conflict-free
            ulonglong2 a01 = *(const ulonglong2*)&xD[d][rbase];    // broadcasts
            ulonglong2 a23 = *(const ulonglong2*)&xD[d][rbase + 2];
            ulonglong2 a45 = *(const ulonglong2*)&xD[d][rbase + 4];
            ulonglong2 a67 = *(const ulonglong2*)&xD[d][rbase + 6];
            acc[0] = fma2(a01.x, w2, acc[0]);
            acc[1] = fma2(a01.y, w2, acc[1]);
            acc[2] = fma2(a23.x, w2, acc[2]);
            acc[3] = fma2(a23.y, w2, acc[3]);
            acc[4] = fma2(a45.x, w2, acc[4]);
            acc[5] = fma2(a45.y, w2, acc[5]);
            acc[6] = fma2(a67.x, w2, acc[6]);
            acc[7] = fma2(a67.y, w2, acc[7]);
        }

        // epilogue: distances + encoding zeros + per-lane running argmin
        const int cg0 = kc0 + cc;
        const float wn0 = wn_s[cc];
        const float wn1 = wn_s[cc + 1];
        #pragma unroll
        for (int r = 0; r < 8; r++) {
            const int row = rbase + r;
            const float xn = xnorm[row];
            float2 dot = unpk(acc[r]);
            float d0 = fmaf(-2.f, dot.x, xn + wn0);
            float d1 = fmaf(-2.f, dot.y, xn + wn1);
            size_t rb = (size_t)(blk * 32 + row) * 1024 + cg0;
            *(float2*)(out + OFF_DIST + rb) = make_float2(d0, d1);
            *(float2*)(out + OFF_ENC + rb) = make_float2(0.f, 0.f);
            if (d0 < vmin[r]) { vmin[r] = d0; imin[r] = cg0; }
            if (d1 < vmin[r]) { vmin[r] = d1; imin[r] = cg0 + 1; }
        }
        __syncthreads();
    }

    // warp-level argmin reduce (col-half partial), then combine halves
    #pragma unroll
    for (int r = 0; r < 8; r++) {
        float v = vmin[r];
        int   ii = imin[r];
        #pragma unroll
        for (int off = 16; off > 0; off >>= 1) {
            float ov = __shfl_down_sync(0xffffffffu, v, off);
            int   oi = __shfl_down_sync(0xffffffffu, ii, off);
            if (ov < v || (ov == v && oi < ii)) { v = ov; ii = oi; }
        }
        if (lane == 0) { hmin[ch2][rbase + r] = v; hidx[ch2][rbase + r] = ii; }
    }
    __syncthreads();

    if (tid < 32) {
        float v0 = hmin[0][tid], v1 = hmin[1][tid];
        int   i0 = hidx[0][tid], i1 = hidx[1][tid];
        bool sel = (v1 < v0) || (v1 == v0 && i1 < i0);
        float v = sel ? v1 : v0;
        int  ii = sel ? i1 : i0;
        rowidx_s[tid] = ii;
        atomicAdd(&g_counts[ii], 1);
        // the '1' in one-hot: ordered after this block's zero-stores by syncthreads
        out[OFF_ENC + (size_t)(blk * 32 + tid) * 1024 + ii] = 1.f;
        // loss: min distance == ||W[idx] - x||^2
        float lv = v;
        #pragma unroll
        for (int off = 16; off > 0; off >>= 1)
            lv += __shfl_down_sync(0xffffffffu, lv, off);
        if (tid == 0) atomicAdd(&g_loss_sum, lv);
    }
    __syncthreads();

    // fused quantized gather: stage W[idx] rows coalesced, write transposed
    #pragma unroll
    for (int i = 0; i < 2; i++) {
        int fid = tid + i * 256;
        int r   = fid >> 4;     // 0..31 (local d index)
        int c4  = fid & 15;
        float4 v = ((const float4*)(W + (size_t)rowidx_s[r] * ED))[c4];
        wq[r][c4 * 4 + 0] = v.x; wq[r][c4 * 4 + 1] = v.y;
        wq[r][c4 * 4 + 2] = v.z; wq[r][c4 * 4 + 3] = v.w;
    }
    __syncthreads();
    {
        const int jb = (blk & 31) * 32;
        #pragma unroll
        for (int i = 0; i < 8; i++) {
            int eid = tid + i * 256;       // 0..2047
            int n   = eid >> 5;
            int dd  = eid & 31;
            out[OFF_Q + ((size_t)(b * ED + n)) * 1024 + jb + dd] = wq[dd][n];
        }
    }
}

// --- kernel 2: scalars -------------------------------------------------------
__global__ void k_final(float* __restrict__ out) {
    __shared__ float red[1024];
    const int k = threadIdx.x;
    const float p = (float)g_counts[k] / 32768.0f;
    red[k] = -p * logf(p + 1e-10f);
    __syncthreads();
    for (int s = 512; s > 0; s >>= 1) {
        if (k < s) red[k] += red[k + s];
        __syncthreads();
    }
    if (k == 0) {
        out[OFF_PERP] = expf(red[0]);
        out[OFF_LOSS] = 0.25f * g_loss_sum / 2097152.0f;
    }
}

// ---------------------------------------------------------------------------
extern "C" void kernel_launch(void* const* d_in, const int* in_sizes, int n_in,
                              void* d_out, int out_size) {
    const float* latent = (const float*)d_in[0];
    const float* W      = (const float*)d_in[1];
    float* out = (float*)d_out;

    k_init <<<4, 256>>>(W);
    k_dist <<<1024, 256>>>(latent, W, out);
    k_final<<<1, 1024>>>(out);
}

// round 5
// speedup vs baseline: 1.3441x; 1.3082x over previous
#include <cuda_runtime.h>
#include <cuda_fp16.h>
#include <cstdint>

#define OFF_Q    0ull
#define OFF_LOSS 2097152ull
#define OFF_PERP 2097153ull
#define OFF_ENC  2097154ull
#define OFF_DIST 35651586ull

#define BSTRIDE 136   // u32 stride: (136 mod 32)=8 -> conflict-free b-frag LDS

__device__ int   g_counts[1024];
__device__ float g_loss_sum;
__device__ float g_wnorm[1024];

static __device__ __forceinline__ void split2(float x, float y,
                                              uint32_t& hi, uint32_t& lo) {
    __half hx = __float2half_rn(x), hy = __float2half_rn(y);
    float rx = x - __half2float(hx), ry = y - __half2float(hy);
    __half2 h = __halves2half2(hx, hy);
    __half2 l = __floats2half2_rn(rx, ry);
    hi = *(uint32_t*)&h;
    lo = *(uint32_t*)&l;
}

static __device__ __forceinline__ void mma16816(float* c, const uint32_t* a,
                                                uint32_t b0, uint32_t b1) {
    asm volatile(
        "mma.sync.aligned.m16n8k16.row.col.f32.f16.f16.f32 "
        "{%0,%1,%2,%3}, {%4,%5,%6,%7}, {%8,%9}, {%0,%1,%2,%3};"
        : "+f"(c[0]), "+f"(c[1]), "+f"(c[2]), "+f"(c[3])
        : "r"(a[0]), "r"(a[1]), "r"(a[2]), "r"(a[3]), "r"(b0), "r"(b1));
}

// --- k_init: codebook norms (8 threads/code) + zero scratch -----------------
__global__ void k_init(const float* __restrict__ W) {
    int t = blockIdx.x * 256 + threadIdx.x;   // 8192 threads
    int code = t >> 3, part = t & 7;
    const float4* wp = (const float4*)(W + (size_t)code * 64);
    float4 v = wp[part * 2], u = wp[part * 2 + 1];
    float s = v.x*v.x + v.y*v.y + v.z*v.z + v.w*v.w
            + u.x*u.x + u.y*u.y + u.z*u.z + u.w*u.w;
    s += __shfl_xor_sync(~0u, s, 1);
    s += __shfl_xor_sync(~0u, s, 2);
    s += __shfl_xor_sync(~0u, s, 4);
    if (part == 0) { g_wnorm[code] = s; g_counts[code] = 0; }
    if (t == 0) g_loss_sum = 0.f;
}

// --- k_main: fused distances(mma) + argmin + enc + quantized + loss --------
__global__ __launch_bounds__(256, 2)
void k_main(const float* __restrict__ latent, const float* __restrict__ W,
            float* __restrict__ out) {
    __shared__ uint32_t s_b[2 * 32 * BSTRIDE];   // B hi | B lo (8704 u32)
    __shared__ float    s_wn[1024];
    __shared__ float    s_rmin[128];
    __shared__ int      s_ridx[128];
    __shared__ float    s_loss[8];

    uint32_t* SBHI = s_b;
    uint32_t* SBLO = s_b + 32 * BSTRIDE;

    const int tid  = threadIdx.x;
    const int blk  = blockIdx.x;
    const int w    = tid >> 5;
    const int lane = tid & 31;
    const int g    = lane >> 2;      // mma group id (row within 8)
    const int tg   = lane & 3;       // thread-in-group
    const int b    = blk >> 3;
    const int jb   = (blk & 7) * 128;

    const int row0 = w * 16 + g;     // local rows this thread owns
    const int row1 = row0 + 8;
    const size_t R0 = (size_t)(blk * 128 + row0);
    const size_t R1 = R0 + 8;

    // load wnorms to smem
    ((float4*)s_wn)[tid] = ((const float4*)g_wnorm)[tid];

    // ---- load A fragments (resident) + row norms ----
    uint32_t ah[4][4], al[4][4];
    float xn0 = 0.f, xn1 = 0.f;
    {
        const float* LB = latent + (size_t)b * 65536 + jb;
        #pragma unroll
        for (int k = 0; k < 4; k++) {
            const int n0 = 16 * k + 2 * tg;
            float x00 = LB[(size_t)(n0    ) * 1024 + row0];
            float x01 = LB[(size_t)(n0 + 1) * 1024 + row0];
            float x10 = LB[(size_t)(n0    ) * 1024 + row1];
            float x11 = LB[(size_t)(n0 + 1) * 1024 + row1];
            float x20 = LB[(size_t)(n0 + 8) * 1024 + row0];
            float x21 = LB[(size_t)(n0 + 9) * 1024 + row0];
            float x30 = LB[(size_t)(n0 + 8) * 1024 + row1];
            float x31 = LB[(size_t)(n0 + 9) * 1024 + row1];
            split2(x00, x01, ah[k][0], al[k][0]);
            split2(x10, x11, ah[k][1], al[k][1]);
            split2(x20, x21, ah[k][2], al[k][2]);
            split2(x30, x31, ah[k][3], al[k][3]);
            xn0 += x00*x00 + x01*x01 + x20*x20 + x21*x21;
            xn1 += x10*x10 + x11*x11 + x30*x30 + x31*x31;
        }
        xn0 += __shfl_xor_sync(~0u, xn0, 1);
        xn0 += __shfl_xor_sync(~0u, xn0, 2);
        xn1 += __shfl_xor_sync(~0u, xn1, 1);
        xn1 += __shfl_xor_sync(~0u, xn1, 2);
    }

    float vmin0 = 3.4e38f, vmin1 = 3.4e38f;
    int   imin0 = 0,       imin1 = 0;

    for (int ch = 0; ch < 8; ch++) {
        __syncthreads();    // previous chunk's mma done -> B smem reusable
        // ---- stage B chunk (128 codes x 64 dims) as fp16 hi/lo pairs ----
        {
            const int code = tid >> 1;
            const int gh   = tid & 1;
            const float4* wp =
                (const float4*)(W + (size_t)(ch * 128 + code) * 64) + gh * 8;
            #pragma unroll
            for (int q = 0; q < 8; q++) {
                float4 v = wp[q];
                uint32_t h0, l0, h1, l1;
                split2(v.x, v.y, h0, l0);
                split2(v.z, v.w, h1, l1);
                const int kp = gh * 16 + q * 2;
                SBHI[(kp    ) * BSTRIDE + code] = h0;
                SBHI[(kp + 1) * BSTRIDE + code] = h1;
                SBLO[(kp    ) * BSTRIDE + code] = l0;
                SBLO[(kp + 1) * BSTRIDE + code] = l1;
            }
        }
        __syncthreads();

        // ---- compute 16 n-tiles in 4 groups of 4 ----
        #pragma unroll
        for (int grp = 0; grp < 4; grp++) {
            float acc[4][4];
            #pragma unroll
            for (int t4 = 0; t4 < 4; t4++) {
                acc[t4][0] = 0.f; acc[t4][1] = 0.f;
                acc[t4][2] = 0.f; acc[t4][3] = 0.f;
            }
            #pragma unroll
            for (int k = 0; k < 4; k++) {
                #pragma unroll
                for (int t4 = 0; t4 < 4; t4++) {
                    const int nb = (grp * 4 + t4) * 8 + g;
                    const int kp = k * 8 + tg;
                    uint32_t bh0 = SBHI[(kp    ) * BSTRIDE + nb];
                    uint32_t bh1 = SBHI[(kp + 4) * BSTRIDE + nb];
                    uint32_t bl0 = SBLO[(kp    ) * BSTRIDE + nb];
                    uint32_t bl1 = SBLO[(kp + 4) * BSTRIDE + nb];
                    mma16816(acc[t4], ah[k], bh0, bh1);   // hi*hi
                    mma16816(acc[t4], al[k], bh0, bh1);   // lo*hi
                    mma16816(acc[t4], ah[k], bl0, bl1);   // hi*lo
                }
            }
            // ---- epilogue for this group ----
            #pragma unroll
            for (int t4 = 0; t4 < 4; t4++) {
                const int col = ch * 128 + (grp * 4 + t4) * 8 + 2 * tg;
                const float2 wn = *(const float2*)&s_wn[col];
                float d00 = fmaf(-2.f, acc[t4][0], xn0 + wn.x);
                float d01 = fmaf(-2.f, acc[t4][1], xn0 + wn.y);
                float d10 = fmaf(-2.f, acc[t4][2], xn1 + wn.x);
                float d11 = fmaf(-2.f, acc[t4][3], xn1 + wn.y);
                const size_t o0 = R0 * 1024 + col;
                const size_t o1 = R1 * 1024 + col;
                *(float2*)(out + OFF_DIST + o0) = make_float2(d00, d01);
                *(float2*)(out + OFF_DIST + o1) = make_float2(d10, d11);
                *(float2*)(out + OFF_ENC  + o0) = make_float2(0.f, 0.f);
                *(float2*)(out + OFF_ENC  + o1) = make_float2(0.f, 0.f);
                if (d00 < vmin0) { vmin0 = d00; imin0 = col; }
                if (d01 < vmin0) { vmin0 = d01; imin0 = col + 1; }
                if (d10 < vmin1) { vmin1 = d10; imin1 = col; }
                if (d11 < vmin1) { vmin1 = d11; imin1 = col + 1; }
            }
        }
    }

    // ---- argmin across tg lanes (rows are warp-exclusive) ----
    #pragma unroll
    for (int off = 1; off <= 2; off <<= 1) {
        float ov0 = __shfl_xor_sync(~0u, vmin0, off);
        int   oi0 = __shfl_xor_sync(~0u, imin0, off);
        if (ov0 < vmin0 || (ov0 == vmin0 && oi0 < imin0)) { vmin0 = ov0; imin0 = oi0; }
        float ov1 = __shfl_xor_sync(~0u, vmin1, off);
        int   oi1 = __shfl_xor_sync(~0u, imin1, off);
        if (ov1 < vmin1 || (ov1 == vmin1 && oi1 < imin1)) { vmin1 = ov1; imin1 = oi1; }
    }
    if (tg == 0) {
        s_rmin[row0] = vmin0; s_ridx[row0] = imin0;
        s_rmin[row1] = vmin1; s_ridx[row1] = imin1;
    }
    __syncthreads();

    if (tid < 128) {
        const int ii = s_ridx[tid];
        atomicAdd(&g_counts[ii], 1);
        // one-hot '1' — ordered after this block's zero stores by syncthreads
        out[OFF_ENC + (size_t)(blk * 128 + tid) * 1024 + ii] = 1.f;
        float v = s_rmin[tid];   // min dist == ||x - W[idx]||^2
        #pragma unroll
        for (int off = 16; off > 0; off >>= 1)
            v += __shfl_down_sync(~0u, v, off);
        if ((tid & 31) == 0) s_loss[tid >> 5] = v;
    }
    __syncthreads();
    if (tid == 0)
        atomicAdd(&g_loss_sum, s_loss[0] + s_loss[1] + s_loss[2] + s_loss[3]);

    // ---- quantized gather: stage W[idx] (stride-129, conflict-free), ----
    // ---- then fully-coalesced transposed writes                       ----
    {
        float* wq = (float*)s_b;     // B region dead now (8704 >= 64*129)
        const int gr = tid >> 1, gh = tid & 1;
        const float4* wp =
            (const float4*)(W + (size_t)s_ridx[gr] * 64) + gh * 8;
        #pragma unroll
        for (int q = 0; q < 8; q++) {
            float4 v = wp[q];
            const int kk = (gh * 8 + q) * 4;
            wq[(kk + 0) * 129 + gr] = v.x;
            wq[(kk + 1) * 129 + gr] = v.y;
            wq[(kk + 2) * 129 + gr] = v.z;
            wq[(kk + 3) * 129 + gr] = v.w;
        }
        __syncthreads();
        float* qb = out + OFF_Q + (size_t)b * 65536 + jb;
        #pragma unroll
        for (int i = 0; i < 32; i++) {
            const int idx = i * 256 + tid;
            const int n = idx >> 7, rr = idx & 127;
            qb[(size_t)n * 1024 + rr] = wq[n * 129 + rr];
        }
    }
}

// --- k_final: perplexity + loss ---------------------------------------------
__global__ void k_final(float* __restrict__ out) {
    __shared__ float red[1024];
    const int k = threadIdx.x;
    const float p = (float)g_counts[k] / 32768.0f;
    red[k] = -p * logf(p + 1e-10f);
    __syncthreads();
    for (int s = 512; s > 0; s >>= 1) {
        if (k < s) red[k] += red[k + s];
        __syncthreads();
    }
    if (k == 0) {
        out[OFF_PERP] = expf(red[0]);
        out[OFF_LOSS] = 0.25f * g_loss_sum / 2097152.0f;
    }
}

// -----------------------------------------------------------------------------
extern "C" void kernel_launch(void* const* d_in, const int* in_sizes, int n_in,
                              void* d_out, int out_size) {
    const float* latent = (const float*)d_in[0];
    const float* W      = (const float*)d_in[1];
    float* out = (float*)d_out;

    k_init <<<32, 256>>>(W);
    k_main <<<256, 256>>>(latent, W, out);
    k_final<<<1, 1024>>>(out);
}

// round 6
// speedup vs baseline: 2.0005x; 1.4883x over previous
#include <cuda_runtime.h>
#include <cuda_fp16.h>
#include <cstdint>

#define OFF_Q    0ull
#define OFF_LOSS 2097152ull
#define OFF_PERP 2097153ull
#define OFF_ENC  2097154ull
#define OFF_DIST 35651586ull

#define BSTRIDE 136   // u32 stride: conflict-free b-frag LDS

__device__ int   g_counts[1024];
__device__ float g_loss_sum;

static __device__ __forceinline__ void split2(float x, float y,
                                              uint32_t& hi, uint32_t& lo) {
    __half hx = __float2half_rn(x), hy = __float2half_rn(y);
    float rx = x - __half2float(hx), ry = y - __half2float(hy);
    __half2 h = __halves2half2(hx, hy);
    __half2 l = __floats2half2_rn(rx, ry);
    hi = *(uint32_t*)&h;
    lo = *(uint32_t*)&l;
}

static __device__ __forceinline__ void mma16816(float* c, const uint32_t* a,
                                                uint32_t b0, uint32_t b1) {
    asm volatile(
        "mma.sync.aligned.m16n8k16.row.col.f32.f16.f16.f32 "
        "{%0,%1,%2,%3}, {%4,%5,%6,%7}, {%8,%9}, {%0,%1,%2,%3};"
        : "+f"(c[0]), "+f"(c[1]), "+f"(c[2]), "+f"(c[3])
        : "r"(a[0]), "r"(a[1]), "r"(a[2]), "r"(a[3]), "r"(b0), "r"(b1));
}

// --- k_main: fused distances(mma) + argmin + enc + quantized + loss --------
__global__ __launch_bounds__(256, 2)
void k_main(const float* __restrict__ latent, const float* __restrict__ W,
            float* __restrict__ out) {
    __shared__ uint32_t s_b[2 * 32 * BSTRIDE];        // B hi | B lo
    __shared__ __align__(16) float s_wn[128];         // chunk code norms
    __shared__ float    s_rmin[128];
    __shared__ int      s_ridx[128];
    __shared__ float    s_loss[8];

    uint32_t* SBHI = s_b;
    uint32_t* SBLO = s_b + 32 * BSTRIDE;

    const int tid  = threadIdx.x;
    const int blk  = blockIdx.x;
    const int w    = tid >> 5;
    const int lane = tid & 31;
    const int g    = lane >> 2;
    const int tg   = lane & 3;
    const int b    = blk >> 3;
    const int jb   = (blk & 7) * 128;

    const int row0 = w * 16 + g;
    const int row1 = row0 + 8;
    const size_t R0 = (size_t)(blk * 128 + row0);
    const size_t R1 = R0 + 8;

    // staging thread mapping
    const int code = tid >> 1;
    const int gh   = tid & 1;

    // ---- load A fragments (resident) + row norms ----
    uint32_t ah[4][4], al[4][4];
    float xn0 = 0.f, xn1 = 0.f;
    {
        const float* LB = latent + (size_t)b * 65536 + jb;
        #pragma unroll
        for (int k = 0; k < 4; k++) {
            const int n0 = 16 * k + 2 * tg;
            float x00 = __ldcs(&LB[(size_t)(n0    ) * 1024 + row0]);
            float x01 = __ldcs(&LB[(size_t)(n0 + 1) * 1024 + row0]);
            float x10 = __ldcs(&LB[(size_t)(n0    ) * 1024 + row1]);
            float x11 = __ldcs(&LB[(size_t)(n0 + 1) * 1024 + row1]);
            float x20 = __ldcs(&LB[(size_t)(n0 + 8) * 1024 + row0]);
            float x21 = __ldcs(&LB[(size_t)(n0 + 9) * 1024 + row0]);
            float x30 = __ldcs(&LB[(size_t)(n0 + 8) * 1024 + row1]);
            float x31 = __ldcs(&LB[(size_t)(n0 + 9) * 1024 + row1]);
            split2(x00, x01, ah[k][0], al[k][0]);
            split2(x10, x11, ah[k][1], al[k][1]);
            split2(x20, x21, ah[k][2], al[k][2]);
            split2(x30, x31, ah[k][3], al[k][3]);
            xn0 += x00*x00 + x01*x01 + x20*x20 + x21*x21;
            xn1 += x10*x10 + x11*x11 + x30*x30 + x31*x31;
        }
        xn0 += __shfl_xor_sync(~0u, xn0, 1);
        xn0 += __shfl_xor_sync(~0u, xn0, 2);
        xn1 += __shfl_xor_sync(~0u, xn1, 1);
        xn1 += __shfl_xor_sync(~0u, xn1, 2);
    }

    // ---- prefetch chunk 0 of B ----
    float4 pf[8];
    {
        const float4* wp = (const float4*)(W + (size_t)code * 64) + gh * 8;
        #pragma unroll
        for (int q = 0; q < 8; q++) pf[q] = wp[q];
    }

    float vmin0 = 3.4e38f, vmin1 = 3.4e38f;
    int   imin0 = 0,       imin1 = 0;
    const float2 zero2 = make_float2(0.f, 0.f);

    for (int ch = 0; ch < 8; ch++) {
        // ---- stage B chunk from prefetch regs: fp16 hi/lo + code norms ----
        {
            float wa = 0.f;
            #pragma unroll
            for (int q = 0; q < 8; q++) {
                float4 v = pf[q];
                uint32_t h0, l0, h1, l1;
                split2(v.x, v.y, h0, l0);
                split2(v.z, v.w, h1, l1);
                const int kp = gh * 16 + q * 2;
                SBHI[(kp    ) * BSTRIDE + code] = h0;
                SBHI[(kp + 1) * BSTRIDE + code] = h1;
                SBLO[(kp    ) * BSTRIDE + code] = l0;
                SBLO[(kp + 1) * BSTRIDE + code] = l1;
                wa = fmaf(v.x, v.x, fmaf(v.y, v.y,
                     fmaf(v.z, v.z, fmaf(v.w, v.w, wa))));
            }
            wa += __shfl_xor_sync(~0u, wa, 1);
            if (gh == 0) s_wn[code] = wa;
        }
        __syncthreads();

        // ---- prefetch next chunk (hidden under mma) ----
        if (ch < 7) {
            const float4* wp =
                (const float4*)(W + (size_t)((ch + 1) * 128 + code) * 64) + gh * 8;
            #pragma unroll
            for (int q = 0; q < 8; q++) pf[q] = wp[q];
        }

        // ---- coalesced streaming zero-fill of this chunk's enc slice ----
        {
            float2* eb = (float2*)(out + OFF_ENC) + (size_t)blk * 65536 + ch * 64;
            #pragma unroll
            for (int i = 0; i < 32; i++) {
                const int idx = i * 256 + tid;
                const int r = idx >> 6, c2 = idx & 63;
                __stcs(eb + (size_t)r * 512 + c2, zero2);
            }
        }

        // ---- compute 16 n-tiles in 4 groups of 4 ----
        #pragma unroll
        for (int grp = 0; grp < 4; grp++) {
            float acc[4][4];
            #pragma unroll
            for (int t4 = 0; t4 < 4; t4++) {
                acc[t4][0] = 0.f; acc[t4][1] = 0.f;
                acc[t4][2] = 0.f; acc[t4][3] = 0.f;
            }
            #pragma unroll
            for (int k = 0; k < 4; k++) {
                #pragma unroll
                for (int t4 = 0; t4 < 4; t4++) {
                    const int nb = (grp * 4 + t4) * 8 + g;
                    const int kp = k * 8 + tg;
                    uint32_t bh0 = SBHI[(kp    ) * BSTRIDE + nb];
                    uint32_t bh1 = SBHI[(kp + 4) * BSTRIDE + nb];
                    uint32_t bl0 = SBLO[(kp    ) * BSTRIDE + nb];
                    uint32_t bl1 = SBLO[(kp + 4) * BSTRIDE + nb];
                    mma16816(acc[t4], ah[k], bh0, bh1);   // hi*hi
                    mma16816(acc[t4], al[k], bh0, bh1);   // lo*hi
                    mma16816(acc[t4], ah[k], bl0, bl1);   // hi*lo
                }
            }
            #pragma unroll
            for (int t4 = 0; t4 < 4; t4++) {
                const int cl  = (grp * 4 + t4) * 8 + 2 * tg;   // col in chunk
                const int col = ch * 128 + cl;                  // global col
                const float2 wn = *(const float2*)&s_wn[cl];
                float d00 = fmaf(-2.f, acc[t4][0], xn0 + wn.x);
                float d01 = fmaf(-2.f, acc[t4][1], xn0 + wn.y);
                float d10 = fmaf(-2.f, acc[t4][2], xn1 + wn.x);
                float d11 = fmaf(-2.f, acc[t4][3], xn1 + wn.y);
                __stcs((float2*)(out + OFF_DIST + R0 * 1024 + col),
                       make_float2(d00, d01));
                __stcs((float2*)(out + OFF_DIST + R1 * 1024 + col),
                       make_float2(d10, d11));
                if (d00 < vmin0) { vmin0 = d00; imin0 = col; }
                if (d01 < vmin0) { vmin0 = d01; imin0 = col + 1; }
                if (d10 < vmin1) { vmin1 = d10; imin1 = col; }
                if (d11 < vmin1) { vmin1 = d11; imin1 = col + 1; }
            }
        }
        __syncthreads();
    }

    // ---- argmin across tg lanes (rows are warp-exclusive) ----
    #pragma unroll
    for (int off = 1; off <= 2; off <<= 1) {
        float ov0 = __shfl_xor_sync(~0u, vmin0, off);
        int   oi0 = __shfl_xor_sync(~0u, imin0, off);
        if (ov0 < vmin0 || (ov0 == vmin0 && oi0 < imin0)) { vmin0 = ov0; imin0 = oi0; }
        float ov1 = __shfl_xor_sync(~0u, vmin1, off);
        int   oi1 = __shfl_xor_sync(~0u, imin1, off);
        if (ov1 < vmin1 || (ov1 == vmin1 && oi1 < imin1)) { vmin1 = ov1; imin1 = oi1; }
    }
    if (tg == 0) {
        s_rmin[row0] = vmin0; s_ridx[row0] = imin0;
        s_rmin[row1] = vmin1; s_ridx[row1] = imin1;
    }
    __syncthreads();

    if (tid < 128) {
        const int ii = s_ridx[tid];
        atomicAdd(&g_counts[ii], 1);
        out[OFF_ENC + (size_t)(blk * 128 + tid) * 1024 + ii] = 1.f;
        float v = s_rmin[tid];
        #pragma unroll
        for (int off = 16; off > 0; off >>= 1)
            v += __shfl_down_sync(~0u, v, off);
        if ((tid & 31) == 0) s_loss[tid >> 5] = v;
    }
    __syncthreads();
    if (tid == 0)
        atomicAdd(&g_loss_sum, s_loss[0] + s_loss[1] + s_loss[2] + s_loss[3]);

    // ---- quantized gather: stride-129 smem stage, coalesced writes ----
    {
        float* wq = (float*)s_b;
        const float4* wp = (const float4*)(W + (size_t)s_ridx[code] * 64) + gh * 8;
        #pragma unroll
        for (int q = 0; q < 8; q++) {
            float4 v = wp[q];
            const int kk = (gh * 8 + q) * 4;
            wq[(kk + 0) * 129 + code] = v.x;
            wq[(kk + 1) * 129 + code] = v.y;
            wq[(kk + 2) * 129 + code] = v.z;
            wq[(kk + 3) * 129 + code] = v.w;
        }
        __syncthreads();
        float* qb = out + OFF_Q + (size_t)b * 65536 + jb;
        #pragma unroll
        for (int i = 0; i < 32; i++) {
            const int idx = i * 256 + tid;
            const int n = idx >> 7, rr = idx & 127;
            __stcs(&qb[(size_t)n * 1024 + rr], wq[n * 129 + rr]);
        }
    }
}

// --- k_final: perplexity + loss; resets scratch for next replay -------------
__global__ void k_final(float* __restrict__ out) {
    __shared__ float red[1024];
    const int k = threadIdx.x;
    const int c = g_counts[k];
    g_counts[k] = 0;                       // replay-invariant reset
    const float p = (float)c / 32768.0f;
    red[k] = -p * logf(p + 1e-10f);
    __syncthreads();
    for (int s = 512; s > 0; s >>= 1) {
        if (k < s) red[k] += red[k + s];
        __syncthreads();
    }
    if (k == 0) {
        out[OFF_PERP] = expf(red[0]);
        out[OFF_LOSS] = 0.25f * g_loss_sum / 2097152.0f;
        g_loss_sum = 0.f;                  // replay-invariant reset
    }
}

// -----------------------------------------------------------------------------
extern "C" void kernel_launch(void* const* d_in, const int* in_sizes, int n_in,
                              void* d_out, int out_size) {
    const float* latent = (const float*)d_in[0];
    const float* W      = (const float*)d_in[1];
    float* out = (float*)d_out;

    k_main <<<256, 256>>>(latent, W, out);
    k_final<<<1, 1024>>>(out);
}

// round 8
// speedup vs baseline: 2.0086x; 1.0040x over previous
#include <cuda_runtime.h>
#include <cuda_fp16.h>
#include <cstdint>

#define OFF_Q    0ull
#define OFF_LOSS 2097152ull
#define OFF_PERP 2097153ull
#define OFF_ENC  2097154ull
#define OFF_DIST 35651586ull

#define BSTRIDE 136   // u32 stride: conflict-free b-frag LDS

__device__ int      g_counts[1024];
__device__ float    g_loss_sum;
__device__ float    g_wnorm[1024];
// codebook packed fp16 hi/lo, layout [chunk(8)][kp(32)][code(128)] u32
__device__ __align__(16) uint32_t g_whi[32768];
__device__ __align__(16) uint32_t g_wlo[32768];

static __device__ __forceinline__ void split2(float x, float y,
                                              uint32_t& hi, uint32_t& lo) {
    __half hx = __float2half_rn(x), hy = __float2half_rn(y);
    float rx = x - __half2float(hx), ry = y - __half2float(hy);
    __half2 h = __halves2half2(hx, hy);
    __half2 l = __floats2half2_rn(rx, ry);
    hi = *(uint32_t*)&h;
    lo = *(uint32_t*)&l;
}

static __device__ __forceinline__ void mma16816(float* c, const uint32_t* a,
                                                uint32_t b0, uint32_t b1) {
    asm volatile(
        "mma.sync.aligned.m16n8k16.row.col.f32.f16.f16.f32 "
        "{%0,%1,%2,%3}, {%4,%5,%6,%7}, {%8,%9}, {%0,%1,%2,%3};"
        : "+f"(c[0]), "+f"(c[1]), "+f"(c[2]), "+f"(c[3])
        : "r"(a[0]), "r"(a[1]), "r"(a[2]), "r"(a[3]), "r"(b0), "r"(b1));
}

// --- k_pre: pack codebook to fp16 hi/lo (smem-ready layout) + wnorms --------
// 32768 threads: t -> code = t>>5, kp(dim pair) = t&31
__global__ void k_pre(const float* __restrict__ W) {
    const int t    = blockIdx.x * 256 + threadIdx.x;
    const int code = t >> 5;
    const int kp   = t & 31;
    float2 v = ((const float2*)(W + (size_t)code * 64))[kp];
    uint32_t h, l;
    split2(v.x, v.y, h, l);
    const int chunk = code >> 7, c = code & 127;
    g_whi[(chunk * 32 + kp) * 128 + c] = h;
    g_wlo[(chunk * 32 + kp) * 128 + c] = l;
    float s = v.x * v.x + v.y * v.y;
    #pragma unroll
    for (int off = 16; off > 0; off >>= 1)
        s += __shfl_xor_sync(~0u, s, off);
    if (kp == 0) g_wnorm[code] = s;
}

// --- k_main: fused distances(mma) + argmin + enc + quantized + loss --------
__global__ __launch_bounds__(256, 2)
void k_main(const float* __restrict__ latent, const float* __restrict__ W,
            float* __restrict__ out) {
    __shared__ __align__(16) uint32_t s_b[2 * 32 * BSTRIDE];   // B hi | B lo
    __shared__ __align__(16) float s_wn[1024];                 // all code norms
    __shared__ float    s_rmin[128];
    __shared__ int      s_ridx[128];
    __shared__ float    s_loss[8];

    uint32_t* SBHI = s_b;
    uint32_t* SBLO = s_b + 32 * BSTRIDE;

    const int tid  = threadIdx.x;
    const int blk  = blockIdx.x;
    const int w    = tid >> 5;
    const int lane = tid & 31;
    const int g    = lane >> 2;
    const int tg   = lane & 3;
    const int b    = blk >> 3;
    const int jb   = (blk & 7) * 128;

    const int row0 = w * 16 + g;
    const int row1 = row0 + 8;
    const size_t R0 = (size_t)(blk * 128 + row0);
    const size_t R1 = R0 + 8;

    // all code norms to smem (once)
    ((float4*)s_wn)[tid] = ((const float4*)g_wnorm)[tid];

    // ---- load A fragments (resident) + row norms ----
    uint32_t ah[4][4], al[4][4];
    float xn0 = 0.f, xn1 = 0.f;
    {
        const float* LB = latent + (size_t)b * 65536 + jb;
        #pragma unroll
        for (int k = 0; k < 4; k++) {
            const int n0 = 16 * k + 2 * tg;
            float x00 = __ldcs(&LB[(size_t)(n0    ) * 1024 + row0]);
            float x01 = __ldcs(&LB[(size_t)(n0 + 1) * 1024 + row0]);
            float x10 = __ldcs(&LB[(size_t)(n0    ) * 1024 + row1]);
            float x11 = __ldcs(&LB[(size_t)(n0 + 1) * 1024 + row1]);
            float x20 = __ldcs(&LB[(size_t)(n0 + 8) * 1024 + row0]);
            float x21 = __ldcs(&LB[(size_t)(n0 + 9) * 1024 + row0]);
            float x30 = __ldcs(&LB[(size_t)(n0 + 8) * 1024 + row1]);
            float x31 = __ldcs(&LB[(size_t)(n0 + 9) * 1024 + row1]);
            split2(x00, x01, ah[k][0], al[k][0]);
            split2(x10, x11, ah[k][1], al[k][1]);
            split2(x20, x21, ah[k][2], al[k][2]);
            split2(x30, x31, ah[k][3], al[k][3]);
            xn0 += x00*x00 + x01*x01 + x20*x20 + x21*x21;
            xn1 += x10*x10 + x11*x11 + x30*x30 + x31*x31;
        }
        xn0 += __shfl_xor_sync(~0u, xn0, 1);
        xn0 += __shfl_xor_sync(~0u, xn0, 2);
        xn1 += __shfl_xor_sync(~0u, xn1, 1);
        xn1 += __shfl_xor_sync(~0u, xn1, 2);
    }

    float vmin0 = 3.4e38f, vmin1 = 3.4e38f;
    int   imin0 = 0,       imin1 = 0;
    const float2 zero2 = make_float2(0.f, 0.f);

    for (int ch = 0; ch < 8; ch++) {
        __syncthreads();   // prev chunk's mma done -> B smem reusable

        // ---- stage prepacked B chunk: coalesced LDG.128 -> STS.128 ----
        {
            const uint4* GH = (const uint4*)(g_whi + ch * 4096);
            const uint4* GL = (const uint4*)(g_wlo + ch * 4096);
            #pragma unroll
            for (int q = 0; q < 4; q++) {
                const int idx = tid + q * 256;          // 0..1023 uint4
                const int kp = idx >> 5, c4 = idx & 31;
                *(uint4*)&SBHI[kp * BSTRIDE + c4 * 4] = GH[idx];
                *(uint4*)&SBLO[kp * BSTRIDE + c4 * 4] = GL[idx];
            }
        }
        __syncthreads();

        // ---- coalesced streaming zero-fill of this chunk's enc slice ----
        {
            float2* eb = (float2*)(out + OFF_ENC) + (size_t)blk * 65536 + ch * 64;
            #pragma unroll
            for (int i = 0; i < 32; i++) {
                const int idx = i * 256 + tid;
                const int r = idx >> 6, c2 = idx & 63;
                __stcs(eb + (size_t)r * 512 + c2, zero2);
            }
        }

        // ---- compute 16 n-tiles in 4 groups of 4 ----
        #pragma unroll
        for (int grp = 0; grp < 4; grp++) {
            float acc[4][4];
            #pragma unroll
            for (int t4 = 0; t4 < 4; t4++) {
                acc[t4][0] = 0.f; acc[t4][1] = 0.f;
                acc[t4][2] = 0.f; acc[t4][3] = 0.f;
            }
            #pragma unroll
            for (int k = 0; k < 4; k++) {
                #pragma unroll
                for (int t4 = 0; t4 < 4; t4++) {
                    const int nb = (grp * 4 + t4) * 8 + g;
                    const int kp = k * 8 + tg;
                    uint32_t bh0 = SBHI[(kp    ) * BSTRIDE + nb];
                    uint32_t bh1 = SBHI[(kp + 4) * BSTRIDE + nb];
                    uint32_t bl0 = SBLO[(kp    ) * BSTRIDE + nb];
                    uint32_t bl1 = SBLO[(kp + 4) * BSTRIDE + nb];
                    mma16816(acc[t4], ah[k], bh0, bh1);   // hi*hi
                    mma16816(acc[t4], al[k], bh0, bh1);   // lo*hi
                    mma16816(acc[t4], ah[k], bl0, bl1);   // hi*lo
                }
            }
            #pragma unroll
            for (int t4 = 0; t4 < 4; t4++) {
                const int col = ch * 128 + (grp * 4 + t4) * 8 + 2 * tg;
                const float2 wn = *(const float2*)&s_wn[col];
                float d00 = fmaf(-2.f, acc[t4][0], xn0 + wn.x);
                float d01 = fmaf(-2.f, acc[t4][1], xn0 + wn.y);
                float d10 = fmaf(-2.f, acc[t4][2], xn1 + wn.x);
                float d11 = fmaf(-2.f, acc[t4][3], xn1 + wn.y);
                __stcs((float2*)(out + OFF_DIST + R0 * 1024 + col),
                       make_float2(d00, d01));
                __stcs((float2*)(out + OFF_DIST + R1 * 1024 + col),
                       make_float2(d10, d11));
                if (d00 < vmin0) { vmin0 = d00; imin0 = col; }
                if (d01 < vmin0) { vmin0 = d01; imin0 = col + 1; }
                if (d10 < vmin1) { vmin1 = d10; imin1 = col; }
                if (d11 < vmin1) { vmin1 = d11; imin1 = col + 1; }
            }
        }
    }

    // ---- argmin across tg lanes (rows are warp-exclusive) ----
    #pragma unroll
    for (int off = 1; off <= 2; off <<= 1) {
        float ov0 = __shfl_xor_sync(~0u, vmin0, off);
        int   oi0 = __shfl_xor_sync(~0u, imin0, off);
        if (ov0 < vmin0 || (ov0 == vmin0 && oi0 < imin0)) { vmin0 = ov0; imin0 = oi0; }
        float ov1 = __shfl_xor_sync(~0u, vmin1, off);
        int   oi1 = __shfl_xor_sync(~0u, imin1, off);
        if (ov1 < vmin1 || (ov1 == vmin1 && oi1 < imin1)) { vmin1 = ov1; imin1 = oi1; }
    }
    if (tg == 0) {
        s_rmin[row0] = vmin0; s_ridx[row0] = imin0;
        s_rmin[row1] = vmin1; s_ridx[row1] = imin1;
    }
    __syncthreads();

    if (tid < 128) {
        const int ii = s_ridx[tid];
        atomicAdd(&g_counts[ii], 1);
        out[OFF_ENC + (size_t)(blk * 128 + tid) * 1024 + ii] = 1.f;
        float v = s_rmin[tid];
        #pragma unroll
        for (int off = 16; off > 0; off >>= 1)
            v += __shfl_down_sync(~0u, v, off);
        if ((tid & 31) == 0) s_loss[tid >> 5] = v;
    }
    __syncthreads();
    if (tid == 0)
        atomicAdd(&g_loss_sum, s_loss[0] + s_loss[1] + s_loss[2] + s_loss[3]);

    // ---- quantized gather: stride-129 smem stage, coalesced writes ----
    {
        float* wq = (float*)s_b;
        const int code = tid >> 1, gh = tid & 1;
        const float4* wp = (const float4*)(W + (size_t)s_ridx[code] * 64) + gh * 8;
        #pragma unroll
        for (int q = 0; q < 8; q++) {
            float4 v = wp[q];
            const int kk = (gh * 8 + q) * 4;
            wq[(kk + 0) * 129 + code] = v.x;
            wq[(kk + 1) * 129 + code] = v.y;
            wq[(kk + 2) * 129 + code] = v.z;
            wq[(kk + 3) * 129 + code] = v.w;
        }
        __syncthreads();
        float* qb = out + OFF_Q + (size_t)b * 65536 + jb;
        #pragma unroll
        for (int i = 0; i < 32; i++) {
            const int idx = i * 256 + tid;
            const int n = idx >> 7, rr = idx & 127;
            __stcs(&qb[(size_t)n * 1024 + rr], wq[n * 129 + rr]);
        }
    }
}

// --- k_final: perplexity + loss (reset happens in k_reset) -------------------
__global__ void k_final(float* __restrict__ out) {
    __shared__ float red[1024];
    const int k = threadIdx.x;
    const float p = (float)g_counts[k] / 32768.0f;
    red[k] = -p * logf(p + 1e-10f);
    __syncthreads();
    for (int s = 512; s > 0; s >>= 1) {
        if (k < s) red[k] += red[k + s];
        __syncthreads();
    }
    if (k == 0) {
        out[OFF_PERP] = expf(red[0]);
        out[OFF_LOSS] = 0.25f * g_loss_sum / 2097152.0f;
    }
}

// --- k_reset: restore zeroed scratch for replay determinism ------------------
__global__ void k_reset() {
    g_counts[blockIdx.x * 256 + threadIdx.x] = 0;
    if (blockIdx.x == 0 && threadIdx.x == 0) g_loss_sum = 0.f;
}

// -----------------------------------------------------------------------------
extern "C" void kernel_launch(void* const* d_in, const int* in_sizes, int n_in,
                              void* d_out, int out_size) {
    const float* latent = (const float*)d_in[0];
    const float* W      = (const float*)d_in[1];
    float* out = (float*)d_out;

    k_pre  <<<128, 256>>>(W);                 // launch idx 4k+0
    k_main <<<256, 256>>>(latent, W, out);    // idx 4k+1 -> ncu -s 5 lands here
    k_final<<<1, 1024>>>(out);                // idx 4k+2
    k_reset<<<4, 256>>>();                    // idx 4k+3
}